// round 13
// baseline (speedup 1.0000x reference)
#include <cuda_runtime.h>
#include <cuda_fp16.h>
#include <cstdint>

// ===========================================================================
// Submanifold 3x3x3 sparse conv, N~1e5, Cin=Cout=64, fp32 in/out.
// R13: SPARSE-COMPACTED fp16 mma.sync implicit GEMM.
//   Site occupancy ~9%: per (tile, tap) only ~12/128 rows hit. Build compact
//   hit lists, mma only ceil(P/16) m16-groups per tap, scatter-add into an
//   fp32 smem accumulator. Each warp owns a disjoint n8 column slice -> no
//   scatter races, no atomics. ~6.3x less tensor work than dense.
// Baseline-PTX only (sm_100 target safe).
// ===========================================================================

#define HASH_BITS 18
#define HASH_SIZE (1u << HASH_BITS)
#define HASH_MASK (HASH_SIZE - 1u)
#define MAX_PROBE 4096
#define MAXN      131072

__device__ unsigned long long g_hkeys[HASH_SIZE];
__device__ int                g_hvals[HASH_SIZE];

// fp16 features [MAXN][64]; fp16 transposed weights pre-swizzled (SW128)
__device__ uint4 g_Af4[MAXN * 64 * 2 / 16];
__device__ uint4 g_Wf4[27 * 8192 / 16];

__device__ __forceinline__ unsigned hash_mix(unsigned long long z) {
    z ^= z >> 30; z *= 0xbf58476d1ce4e5b9ULL;
    z ^= z >> 27; z *= 0x94d049bb133111ebULL;
    z ^= z >> 31;
    return (unsigned)z & HASH_MASK;
}

#define SW128(off) ((off) ^ (((off) >> 3) & 0x70))

// ---- fused prep: hash init + feat->fp16 + weight transpose/swizzle ----
__global__ void fused_prep_kernel(const float4* __restrict__ feat4, int total4,
                                  const float* __restrict__ weight, int welems) {
    int i = blockIdx.x * blockDim.x + threadIdx.x;
    if (i < (int)HASH_SIZE) { g_hkeys[i] = ~0ULL; g_hvals[i] = 0x7fffffff; }
    if (i < total4) {
        float4 x = feat4[i];
        __half2 lo = __floats2half2_rn(x.x, x.y);
        __half2 hi = __floats2half2_rn(x.z, x.w);
        ((uint2*)g_Af4)[i] = make_uint2(*(unsigned*)&lo, *(unsigned*)&hi);
    }
    if (i < 27 * 4096) {
        int k    = i >> 12;
        int cin  = (i >> 6) & 63;
        int cout = i & 63;
        float x = (i < welems) ? weight[i] : 0.0f;
        unsigned off = SW128((unsigned)(cout * 128 + cin * 2));
        ((__half*)g_Wf4)[((unsigned)k * 8192 + off) >> 1] = __float2half_rn(x);
    }
}

__global__ void hash_insert_kernel(const int* __restrict__ coords,
                                   const int* __restrict__ batch_idx,
                                   int n, int coords_elems, int batch_elems) {
    int i = blockIdx.x * blockDim.x + threadIdx.x;
    if (i >= n) return;
    int c0 = (3 * i + 0 < coords_elems) ? coords[3 * i + 0] : 0;
    int c1 = (3 * i + 1 < coords_elems) ? coords[3 * i + 1] : 0;
    int c2 = (3 * i + 2 < coords_elems) ? coords[3 * i + 2] : 0;
    int b  = (i < batch_elems) ? batch_idx[i] : 0;
    long long x = (long long)c0 + (long long)b * 100000LL;
    unsigned long long key = ((unsigned long long)x << 40) |
                             ((unsigned long long)(long long)c1 << 20) |
                             ((unsigned long long)(long long)c2);
    unsigned s = hash_mix(key);
    for (int p = 0; p < MAX_PROBE; p++) {
        unsigned long long prev = atomicCAS(&g_hkeys[s & HASH_MASK], ~0ULL, key);
        if (prev == ~0ULL || prev == key) {
            atomicMin(&g_hvals[s & HASH_MASK], i);   // min-index tie-break
            return;
        }
        s = (s + 1) & HASH_MASK;
    }
}

__device__ __forceinline__ int hash_lookup(unsigned long long key, int n) {
    unsigned s = hash_mix(key);
    for (int p = 0; p < MAX_PROBE; p++) {
        unsigned long long k = g_hkeys[s & HASH_MASK];
        if (k == key) {
            int v = g_hvals[s & HASH_MASK];
            return (v >= 0 && v < n) ? v : -1;
        }
        if (k == ~0ULL) return -1;
        s = (s + 1) & HASH_MASK;
    }
    return -1;
}

__global__ void zero_out_kernel(float* out, int nelem) {
    int i = blockIdx.x * blockDim.x + threadIdx.x;
    if (i < nelem) out[i] = 0.0f;
}

// ===========================================================================
// Sparse-compacted conv kernel. One block = 128-row tile, 256 threads.
// smem layout (dynamic):
//   acc   : 128 x 66 f32                 @ 0       (33792 B)
//   A[2]  : 128 rows x 128B SW128        @ 33792   (2 x 16384)
//   B[2]  : 64 rows x 128B (W tap)       @ 66560   (2 x 8192)
//   cnt   : 27 ints (pad 128B)           @ 82944
//   rows  : uint8 [27][128]              @ 83072   (3456)
//   nbs   : int   [27][128]              @ 86528   (13824)
// ===========================================================================

#define ACC_STRIDE 66
#define SM_ACC     0u
#define SM_A(buf)  (33792u + (unsigned)(buf) * 16384u)
#define SM_B(buf)  (66560u + (unsigned)(buf) * 8192u)
#define SM_CNT     82944u
#define SM_ROWS    83072u
#define SM_NBS     86528u
#define SMEM_TOTAL (86528 + 13824)

__device__ __forceinline__ unsigned smem_u32(const void* p) {
    unsigned a;
    asm("{ .reg .u64 t; cvta.to.shared.u64 t, %1; cvt.u32.u64 %0, t; }"
        : "=r"(a) : "l"(p));
    return a;
}
__device__ __forceinline__ void ldsm_x4(unsigned addr, unsigned r[4]) {
    asm volatile("ldmatrix.sync.aligned.m8n8.x4.shared.b16 {%0,%1,%2,%3}, [%4];"
                 : "=r"(r[0]), "=r"(r[1]), "=r"(r[2]), "=r"(r[3]) : "r"(addr));
}
__device__ __forceinline__ void ldsm_x2(unsigned addr, unsigned r[2]) {
    asm volatile("ldmatrix.sync.aligned.m8n8.x2.shared.b16 {%0,%1}, [%2];"
                 : "=r"(r[0]), "=r"(r[1]) : "r"(addr));
}

__global__ __launch_bounds__(256, 2)
void subm_conv_sp_kernel(const int*   __restrict__ coords,
                         const int*   __restrict__ batch_idx,
                         float*       __restrict__ out,
                         int n, int coords_elems, int batch_elems) {
    extern __shared__ char smem[];
    const unsigned sbase = smem_u32(smem);
    const int tid  = threadIdx.x;
    const int wid  = tid >> 5;
    const int lane = tid & 31;
    const int row0 = blockIdx.x * 128;

    float*         accS  = (float*)(smem + SM_ACC);
    int*           cntS  = (int*)(smem + SM_CNT);
    unsigned char* rowsS = (unsigned char*)(smem + SM_ROWS);
    int*           nbsS  = (int*)(smem + SM_NBS);

    // ---- zero acc, init counters ----
    for (int i = tid; i < 128 * ACC_STRIDE; i += 256) accS[i] = 0.0f;
    if (tid < 27) cntS[tid] = 0;
    __syncthreads();

    // ---- build compact hit lists per tap (racy order; values order-free) ----
    for (int e = tid; e < 27 * 128; e += 256) {
        int k = e >> 7;
        int r = e & 127;
        int row = row0 + r;
        if (row < n) {
            int dx = (k / 9) - 1, dy = ((k / 3) % 3) - 1, dz = (k % 3) - 1;
            int c0 = (3 * row + 0 < coords_elems) ? coords[3 * row + 0] : 0;
            int c1 = (3 * row + 1 < coords_elems) ? coords[3 * row + 1] : 0;
            int c2 = (3 * row + 2 < coords_elems) ? coords[3 * row + 2] : 0;
            int b  = (row < batch_elems) ? batch_idx[row] : 0;
            long long x = (long long)c0 + (long long)b * 100000LL + dx;
            long long y = (long long)c1 + dy;
            long long z = (long long)c2 + dz;
            unsigned long long key = ((unsigned long long)x << 40) |
                                     ((unsigned long long)y << 20) |
                                     ((unsigned long long)z);
            int nb = hash_lookup(key, n);
            if (nb >= 0) {
                int pos = atomicAdd(&cntS[k], 1);
                rowsS[k * 128 + pos] = (unsigned char)r;
                nbsS[k * 128 + pos]  = nb;
            }
        }
    }
    __syncthreads();
    // pad each list to multiple of 16 (row=255 sentinel, nb=0)
    if (tid < 27) {
        int P = cntS[tid];
        int Ppad = (P + 15) & ~15;
        for (int i = P; i < Ppad; i++) {
            rowsS[tid * 128 + i] = 255;
            nbsS[tid * 128 + i]  = 0;
        }
    }
    __syncthreads();

    const __half* Af = (const __half*)g_Af4;

    // Stage tap kk: gather Ppad compacted rows (8x16B each) + W tap (512x16B)
#define STAGE_TAP(kk, buf)                                                    \
    {                                                                         \
        int P    = cntS[kk];                                                  \
        int nch  = (((P + 15) & ~15)) * 8;                                    \
        const int* nb_k = &nbsS[(kk) * 128];                                  \
        for (int idx = tid; idx < nch; idx += 256) {                          \
            int r = idx >> 3, ch = idx & 7;                                   \
            int nb = nb_k[r];                                                 \
            const void* gsrc = Af + (size_t)nb * 64 + ch * 8;                 \
            unsigned daddr = sbase + SM_A(buf) +                              \
                             SW128((unsigned)(r * 128 + ch * 16));            \
            asm volatile("cp.async.ca.shared.global [%0], [%1], 16;"          \
                         :: "r"(daddr), "l"(gsrc) : "memory");                \
        }                                                                     \
        _Pragma("unroll")                                                     \
        for (int q = 0; q < 2; q++) {                                         \
            int e = tid + q * 256;                                            \
            const uint4* src = g_Wf4 + (kk) * 512 + e;                        \
            unsigned daddr = sbase + SM_B(buf) + e * 16;                      \
            asm volatile("cp.async.ca.shared.global [%0], [%1], 16;"          \
                         :: "r"(daddr), "l"(src) : "memory");                 \
        }                                                                     \
        asm volatile("cp.async.commit_group;" ::: "memory");                  \
    }

    STAGE_TAP(0, 0)

    const int nb8   = wid * 8;            // warp's exclusive n8 column slice
    const int a_row = lane & 15;
    const int a_kc  = lane >> 4;
    const int b_rw  = lane & 7;
    const int b_kc  = (lane >> 3) & 1;

    for (int k = 0; k < 27; k++) {
        const int buf = k & 1;
        asm volatile("cp.async.wait_group 0;" ::: "memory");
        __syncthreads();   // tap k staged & all warps past compute(k-1)

        if (k + 1 < 27) STAGE_TAP(k + 1, (k + 1) & 1)

        const int P  = cntS[k];
        const int ng = (P + 15) >> 4;
        const unsigned abase = sbase + SM_A(buf);
        const unsigned bbase = sbase + SM_B(buf);
        const unsigned char* rw_k = &rowsS[k * 128];

        for (int g = 0; g < ng; g++) {
            float c0 = 0.f, c1 = 0.f, c2 = 0.f, c3 = 0.f;
#pragma unroll
            for (int kc = 0; kc < 4; kc++) {
                unsigned af[4];
                unsigned aoff = (unsigned)((g * 16 + a_row) * 128 +
                                           (kc * 2 + a_kc) * 16);
                ldsm_x4(abase + SW128(aoff), af);
                unsigned bf[2];
                unsigned boff = (unsigned)((nb8 + b_rw) * 128 +
                                           (kc * 2 + b_kc) * 16);
                ldsm_x2(bbase + SW128(boff), bf);
                asm volatile(
                    "mma.sync.aligned.m16n8k16.row.col.f32.f16.f16.f32 "
                    "{%0,%1,%2,%3}, {%4,%5,%6,%7}, {%8,%9}, {%0,%1,%2,%3};"
                    : "+f"(c0), "+f"(c1), "+f"(c2), "+f"(c3)
                    : "r"(af[0]), "r"(af[1]), "r"(af[2]), "r"(af[3]),
                      "r"(bf[0]), "r"(bf[1]));
            }
            // scatter-add into fp32 smem acc (warp-exclusive columns)
            int r0c = g * 16 + (lane >> 2);
            int r1c = r0c + 8;
            unsigned rA = rw_k[r0c];
            unsigned rB = rw_k[r1c];
            int coff = nb8 + (lane & 3) * 2;
            if (rA != 255u) {
                float2* p = (float2*)&accS[rA * ACC_STRIDE + coff];
                float2 v = *p; v.x += c0; v.y += c1; *p = v;
            }
            if (rB != 255u) {
                float2* p = (float2*)&accS[rB * ACC_STRIDE + coff];
                float2 v = *p; v.x += c2; v.y += c3; *p = v;
            }
        }
    }

    __syncthreads();
    // ---- writeout acc -> out ----
    for (int i = tid; i < 128 * 32; i += 256) {
        int r  = i >> 5;
        int c2i = i & 31;
        int row = row0 + r;
        if (row < n) {
            float2 v = *(float2*)&accS[r * ACC_STRIDE + c2i * 2];
            *(float2*)(out + (size_t)row * 64 + c2i * 2) = v;
        }
    }
}

// ---------------------------------------------------------------------------
// Launch. Binding inferred from in_sizes ratios (unit-agnostic), as in R6.
// ---------------------------------------------------------------------------
extern "C" void kernel_launch(void* const* d_in, const int* in_sizes, int n_in,
                              void* d_out, int out_size) {
    float* out = (float*)d_out;

    int wi = -1;
    bool bytes_mode = false;
    for (int i = 0; i < n_in; i++) {
        if (in_sizes[i] == 27 * 64 * 64)          { wi = i; bytes_mode = false; }
        else if (in_sizes[i] == 27 * 64 * 64 * 4) { wi = i; bytes_mode = true;  }
    }
    int bi = -1, ci = -1, fi = -1;
    for (int b = 0; b < n_in && bi < 0; b++) {
        if (b == wi) continue;
        long long s = in_sizes[b];
        if (s <= 0) continue;
        int c = -1, f = -1;
        for (int j = 0; j < n_in; j++) {
            if (j == b || j == wi) continue;
            if ((long long)in_sizes[j] == s * 3)  c = j;
            if ((long long)in_sizes[j] == s * 64) f = j;
        }
        if (c >= 0 && f >= 0) { bi = b; ci = c; fi = f; }
    }

    if (wi < 0 || bi < 0) {
        int nelem = out_size > 0 ? out_size : 1;
        zero_out_kernel<<<(nelem + 255) / 256, 256>>>(out, nelem);
        return;
    }

    const int div          = bytes_mode ? 4 : 1;
    const int n            = in_sizes[bi] / div;
    const int batch_elems  = in_sizes[bi] / div;
    const int coords_elems = in_sizes[ci] / div;
    const int feat_elems   = in_sizes[fi] / div;
    const int weight_elems = in_sizes[wi] / div;

    if (n <= 0 || n > MAXN) {
        int nelem = out_size > 0 ? out_size : 1;
        zero_out_kernel<<<(nelem + 255) / 256, 256>>>(out, nelem);
        return;
    }

    const float* feat   = (const float*)d_in[fi];
    const int*   coords = (const int*)d_in[ci];
    const int*   batch  = (const int*)d_in[bi];
    const float* weight = (const float*)d_in[wi];

    // Idempotent, no static guards; non-stream API is capture-safe.
    cudaFuncSetAttribute(subm_conv_sp_kernel,
                         cudaFuncAttributeMaxDynamicSharedMemorySize,
                         SMEM_TOTAL);

    const int feat4 = feat_elems / 4;
    int prep_threads = feat4;
    if ((int)HASH_SIZE > prep_threads) prep_threads = HASH_SIZE;
    if (27 * 4096 > prep_threads)      prep_threads = 27 * 4096;

    fused_prep_kernel<<<(prep_threads + 255) / 256, 256>>>(
        (const float4*)feat, feat4, weight, weight_elems);
    hash_insert_kernel<<<(n + 255) / 256, 256>>>(coords, batch, n,
                                                 coords_elems, batch_elems);
    subm_conv_sp_kernel<<<(n + 127) / 128, 256, SMEM_TOTAL>>>(
        coords, batch, out, n, coords_elems, batch_elems);
}